// round 6
// baseline (speedup 1.0000x reference)
#include <cuda_runtime.h>
#include <cuda_bf16.h>
#include <cuda_fp8.h>
#include <cstdint>

#define N 8192
#define D 128
#define BM 128
#define BN 128
#define NT_TILES 64
#define NUM_TRI (NT_TILES * (NT_TILES + 1) / 2)   // 2080
#define SSTRB 144                                  // 128B row + 16B pad (4-bank skew)
#define SMEM_BYTES (2 * BM * SSTRB)                // 36864
#define PGRID 304                                  // 2 * 152 SMs (persistent)

// -------- device scratch --------
__device__ uint8_t g_zn8[N * D];     // normalized nodes, e4m3
__device__ float g_sumz[D];
__device__ float g_sumzp[D];
__device__ float g_den[N];
__device__ unsigned int g_ctr;

// -------- kernel 1: normalize rows -> e4m3, column sums, zero scratch --------
__global__ void prep_kernel(const float* __restrict__ nodes,
                            const float* __restrict__ pairn) {
    __shared__ float s_col[D];
    int tid = threadIdx.x;
    if (tid < D) s_col[tid] = 0.f;
    if (blockIdx.x < (N / 256)) g_den[blockIdx.x * 256 + tid] = 0.f;
    if (blockIdx.x == 0) {
        if (tid < D) { g_sumz[tid] = 0.f; g_sumzp[tid] = 0.f; }
        if (tid == 0) g_ctr = 0u;
    }
    __syncthreads();

    int warp = tid >> 5, lane = tid & 31;
    bool is_pair = blockIdx.x >= (N / 8);
    int row = (blockIdx.x - (is_pair ? (N / 8) : 0)) * 8 + warp;
    const float* src = is_pair ? pairn : nodes;

    float4 v = reinterpret_cast<const float4*>(src + (size_t)row * D)[lane];
    float sq = v.x * v.x + v.y * v.y + v.z * v.z + v.w * v.w;
#pragma unroll
    for (int o = 16; o > 0; o >>= 1) sq += __shfl_xor_sync(0xffffffffu, sq, o);
    float scale = 1.0f / fmaxf(sqrtf(sq), 1e-12f);
    float z0 = v.x * scale, z1 = v.y * scale, z2 = v.z * scale, z3 = v.w * scale;

    if (!is_pair) {
        unsigned short lo = __nv_cvt_float2_to_fp8x2(make_float2(z0, z1),
                                                     __NV_SATFINITE, __NV_E4M3);
        unsigned short hi = __nv_cvt_float2_to_fp8x2(make_float2(z2, z3),
                                                     __NV_SATFINITE, __NV_E4M3);
        reinterpret_cast<uint32_t*>(g_zn8)[row * 32 + lane] =
            (uint32_t)lo | ((uint32_t)hi << 16);
    }
    atomicAdd(&s_col[lane * 4 + 0], z0);
    atomicAdd(&s_col[lane * 4 + 1], z1);
    atomicAdd(&s_col[lane * 4 + 2], z2);
    atomicAdd(&s_col[lane * 4 + 3], z3);
    __syncthreads();
    if (tid < D) atomicAdd(is_pair ? &g_sumzp[tid] : &g_sumz[tid], s_col[tid]);
}

// -------- mma helpers --------
__device__ __forceinline__ void ldmx4(uint32_t r[4], uint32_t addr) {
    asm volatile("ldmatrix.sync.aligned.m8n8.x4.shared.b16 {%0,%1,%2,%3}, [%4];\n"
                 : "=r"(r[0]), "=r"(r[1]), "=r"(r[2]), "=r"(r[3]) : "r"(addr));
}
__device__ __forceinline__ void mma16832(float c[4], const uint32_t a[4], const uint32_t b[2]) {
    asm volatile("mma.sync.aligned.m16n8k32.row.col.f32.e4m3.e4m3.f32 "
                 "{%0,%1,%2,%3}, {%4,%5,%6,%7}, {%8,%9}, {%0,%1,%2,%3};\n"
                 : "+f"(c[0]), "+f"(c[1]), "+f"(c[2]), "+f"(c[3])
                 : "r"(a[0]), "r"(a[1]), "r"(a[2]), "r"(a[3]), "r"(b[0]), "r"(b[1]));
}

// -------- kernel 2: persistent; triangular tiles of S = ZN@ZN^T (fp8),
//          fused exp row/col sums, last-exit finalize --------
__global__ void __launch_bounds__(256, 2) simexp_kernel(float* __restrict__ out) {
    extern __shared__ uint8_t smem[];
    uint8_t* sA = smem;
    uint8_t* sB = smem + BM * SSTRB;
    __shared__ float s_red[8];
    __shared__ int s_last;

    const int tid = threadIdx.x;
    const int warp = tid >> 5, lane = tid & 31;
    const uint32_t aBase = (uint32_t)__cvta_generic_to_shared(sA);
    const uint32_t bBase = (uint32_t)__cvta_generic_to_shared(sB);
    const int wm = (warp >> 1) * 32;     // 4 warps along M
    const int wn = (warp & 1) * 64;      // 2 warps along N

    for (int t = blockIdx.x; t < NUM_TRI; t += PGRID) {
        // triangular decode t -> (ti, tj), tj >= ti
        int ti = (int)((129.0f - sqrtf(16641.0f - 8.0f * (float)t)) * 0.5f);
        if (ti > 0 && ti * (2 * NT_TILES + 1 - ti) / 2 > t) ti--;
        while ((ti + 1) * (2 * NT_TILES + 1 - (ti + 1)) / 2 <= t) ti++;
        const int tj = ti + (t - ti * (2 * NT_TILES + 1 - ti) / 2);
        const int i0 = ti * BM;
        const int j0 = tj * BN;
        const bool offdiag = (tj != ti);

        __syncthreads();   // protect smem from previous iteration's readers

        // cooperative tile loads: 128 rows x 128B, 16B vectors
        {
            const int r = tid >> 3;          // 0..31
            const int seg = tid & 7;         // 16B segment
            const uint4* gA = reinterpret_cast<const uint4*>(g_zn8 + (size_t)i0 * D);
            const uint4* gB = reinterpret_cast<const uint4*>(g_zn8 + (size_t)j0 * D);
#pragma unroll
            for (int rr = 0; rr < 4; rr++) {
                int row = r + rr * 32;
                uint4 va = gA[row * 8 + seg];
                uint4 vb = gB[row * 8 + seg];
                *reinterpret_cast<uint4*>(sA + row * SSTRB + seg * 16) = va;
                *reinterpret_cast<uint4*>(sB + row * SSTRB + seg * 16) = vb;
            }
        }
        __syncthreads();

        float acc[2][8][4];
#pragma unroll
        for (int mt = 0; mt < 2; mt++)
#pragma unroll
            for (int nt = 0; nt < 8; nt++)
#pragma unroll
                for (int q = 0; q < 4; q++) acc[mt][nt][q] = 0.f;

#pragma unroll
        for (int kt = 0; kt < 4; kt++) {
            const int k0 = kt * 32;          // byte offset along K
            uint32_t afr[2][4];
#pragma unroll
            for (int mt = 0; mt < 2; mt++) {
                int row = wm + mt * 16 + (lane & 15);
                int kb = k0 + (lane >> 4) * 16;
                ldmx4(afr[mt], aBase + (uint32_t)(row * SSTRB + kb));
            }
            uint32_t bfr[8][2];
#pragma unroll
            for (int np = 0; np < 4; np++) {     // each x4 covers two n8-tiles
                int g = lane >> 3;
                int nrow = wn + np * 16 + (g >> 1) * 8 + (lane & 7);
                int kb = k0 + (g & 1) * 16;
                uint32_t r4[4];
                ldmx4(r4, bBase + (uint32_t)(nrow * SSTRB + kb));
                bfr[np * 2 + 0][0] = r4[0]; bfr[np * 2 + 0][1] = r4[1];
                bfr[np * 2 + 1][0] = r4[2]; bfr[np * 2 + 1][1] = r4[3];
            }
#pragma unroll
            for (int mt = 0; mt < 2; mt++)
#pragma unroll
                for (int nt = 0; nt < 8; nt++)
                    mma16832(acc[mt][nt], afr[mt], bfr[nt]);
        }

        // epilogue: e = exp(2*s); row sums -> g_den[i..]; col sums when offdiag
        const int rbase = i0 + wm + (lane >> 2);
        const int cbase = j0 + wn + 2 * (lane & 3);

        float ccol[8][2];
#pragma unroll
        for (int nt = 0; nt < 8; nt++) { ccol[nt][0] = 0.f; ccol[nt][1] = 0.f; }

#pragma unroll
        for (int mt = 0; mt < 2; mt++) {
#pragma unroll
            for (int half = 0; half < 2; half++) {
                int grow = rbase + mt * 16 + half * 8;
                float p = 0.f;
#pragma unroll
                for (int nt = 0; nt < 8; nt++) {
                    int gc0 = cbase + nt * 8;
                    float s0 = acc[mt][nt][half * 2 + 0];
                    float s1 = acc[mt][nt][half * 2 + 1];
                    float e0 = (grow != gc0)     ? __expf(2.0f * s0) : 0.f;
                    float e1 = (grow != gc0 + 1) ? __expf(2.0f * s1) : 0.f;
                    p += e0 + e1;
                    ccol[nt][0] += e0;
                    ccol[nt][1] += e1;
                }
                p += __shfl_xor_sync(0xffffffffu, p, 1);
                p += __shfl_xor_sync(0xffffffffu, p, 2);
                if ((lane & 3) == 0) atomicAdd(&g_den[grow], p);
            }
        }

        if (offdiag) {
#pragma unroll
            for (int nt = 0; nt < 8; nt++) {
#pragma unroll
                for (int c = 0; c < 2; c++) {
                    float v = ccol[nt][c];
                    v += __shfl_xor_sync(0xffffffffu, v, 4);
                    v += __shfl_xor_sync(0xffffffffu, v, 8);
                    v += __shfl_xor_sync(0xffffffffu, v, 16);
                    if (lane < 4) atomicAdd(&g_den[j0 + wn + nt * 8 + 2 * lane + c], v);
                }
            }
        }
    }

    // ---- once per block: last-exit finalize ----
    if (tid == 0) {
        __threadfence();
        s_last = (atomicAdd(&g_ctr, 1u) == (unsigned)(gridDim.x - 1));
    }
    __syncthreads();
    if (s_last) {
        __threadfence();
        float lg = 0.f;
        for (int i = tid; i < N; i += 256) lg += __logf(__ldcg(&g_den[i]));
        if (tid < D) lg -= (2.0f / (float)N) * g_sumz[tid] * g_sumzp[tid];
#pragma unroll
        for (int o = 16; o > 0; o >>= 1) lg += __shfl_xor_sync(0xffffffffu, lg, o);
        if ((tid & 31) == 0) s_red[warp] = lg;
        __syncthreads();
        if (tid == 0) {
            float tot = 0.f;
#pragma unroll
            for (int w = 0; w < 8; w++) tot += s_red[w];
            out[0] = tot;
        }
    }
}

extern "C" void kernel_launch(void* const* d_in, const int* in_sizes, int n_in,
                              void* d_out, int out_size) {
    const float* nodes = (const float*)d_in[0];
    const float* pairn = (const float*)d_in[1];
    float* out = (float*)d_out;

    cudaFuncSetAttribute(simexp_kernel, cudaFuncAttributeMaxDynamicSharedMemorySize, SMEM_BYTES);

    prep_kernel<<<2 * (N / 8), 256>>>(nodes, pairn);
    simexp_kernel<<<PGRID, 256, SMEM_BYTES>>>(out);
}

// round 8
// speedup vs baseline: 1.6233x; 1.6233x over previous
#include <cuda_runtime.h>
#include <cuda_bf16.h>
#include <cstdint>

#define N 8192
#define D 128
#define BM 128
#define BN 128
#define NT_TILES 64
#define NUM_TRI (NT_TILES * (NT_TILES + 1) / 2)   // 2080
#define SSTRIDE 136                                // 128 + 8 bf16 pad
#define SMEM_BYTES (2 * BM * SSTRIDE * 2)          // 69632

// -------- device scratch --------
__device__ __nv_bfloat16 g_zn[N * D];
struct Scratch { float sumz[D]; float sumzp[D]; float den[N]; };
__device__ Scratch g_s;

// -------- kernel 1: normalize rows -> bf16, column sums --------
__global__ void prep_kernel(const float* __restrict__ nodes,
                            const float* __restrict__ pairn) {
    __shared__ float s_col[D];
    int tid = threadIdx.x;
    if (tid < D) s_col[tid] = 0.f;
    __syncthreads();

    int warp = tid >> 5, lane = tid & 31;
    bool is_pair = blockIdx.x >= (N / 8);
    int row = (blockIdx.x - (is_pair ? (N / 8) : 0)) * 8 + warp;
    const float* src = is_pair ? pairn : nodes;

    float4 v = reinterpret_cast<const float4*>(src + (size_t)row * D)[lane];
    float sq = v.x * v.x + v.y * v.y + v.z * v.z + v.w * v.w;
#pragma unroll
    for (int o = 16; o > 0; o >>= 1) sq += __shfl_xor_sync(0xffffffffu, sq, o);
    float scale = 1.0f / fmaxf(sqrtf(sq), 1e-12f);
    float z0 = v.x * scale, z1 = v.y * scale, z2 = v.z * scale, z3 = v.w * scale;

    if (!is_pair) {
        __nv_bfloat162* dst = reinterpret_cast<__nv_bfloat162*>(g_zn + (size_t)row * D);
        dst[lane * 2 + 0] = __floats2bfloat162_rn(z0, z1);
        dst[lane * 2 + 1] = __floats2bfloat162_rn(z2, z3);
    }
    atomicAdd(&s_col[lane * 4 + 0], z0);
    atomicAdd(&s_col[lane * 4 + 1], z1);
    atomicAdd(&s_col[lane * 4 + 2], z2);
    atomicAdd(&s_col[lane * 4 + 3], z3);
    __syncthreads();
    if (tid < D) atomicAdd(is_pair ? &g_s.sumzp[tid] : &g_s.sumz[tid], s_col[tid]);
}

// -------- mma helpers --------
__device__ __forceinline__ void ldmx4(uint32_t r[4], uint32_t addr) {
    asm volatile("ldmatrix.sync.aligned.m8n8.x4.shared.b16 {%0,%1,%2,%3}, [%4];\n"
                 : "=r"(r[0]), "=r"(r[1]), "=r"(r[2]), "=r"(r[3]) : "r"(addr));
}
__device__ __forceinline__ void mma16816(float c[4], const uint32_t a[4],
                                         uint32_t b0, uint32_t b1) {
    asm volatile("mma.sync.aligned.m16n8k16.row.col.f32.bf16.bf16.f32 "
                 "{%0,%1,%2,%3}, {%4,%5,%6,%7}, {%8,%9}, {%0,%1,%2,%3};\n"
                 : "+f"(c[0]), "+f"(c[1]), "+f"(c[2]), "+f"(c[3])
                 : "r"(a[0]), "r"(a[1]), "r"(a[2]), "r"(a[3]), "r"(b0), "r"(b1));
}

// -------- kernel 2: triangular tiles of S = ZN@ZN^T, fused exp, symmetry --------
__global__ void __launch_bounds__(512, 2) simexp_kernel() {
    extern __shared__ __nv_bfloat16 smem[];
    __nv_bfloat16* sA = smem;
    __nv_bfloat16* sB = smem + BM * SSTRIDE;

    const int tid = threadIdx.x;
    const int warp = tid >> 5, lane = tid & 31;

    // triangular decode t -> (ti, tj), tj >= ti
    const int t = blockIdx.x;
    int ti = (int)((129.0f - sqrtf(16641.0f - 8.0f * (float)t)) * 0.5f);
    if (ti > 0 && ti * (2 * NT_TILES + 1 - ti) / 2 > t) ti--;
    while ((ti + 1) * (2 * NT_TILES + 1 - (ti + 1)) / 2 <= t) ti++;
    const int tj = ti + (t - ti * (2 * NT_TILES + 1 - ti) / 2);
    const int i0 = ti * BM;
    const int j0 = tj * BN;
    const bool offdiag = (tj != ti);

    // cooperative tile loads: 512 threads, 16B vectors
    {
        const int r = tid >> 4;          // 0..31
        const int seg = tid & 15;        // 16B segment
        const uint4* gA = reinterpret_cast<const uint4*>(g_zn + (size_t)i0 * D);
        const uint4* gB = reinterpret_cast<const uint4*>(g_zn + (size_t)j0 * D);
#pragma unroll
        for (int rr = 0; rr < 4; rr++) {
            int row = r + rr * 32;
            uint4 va = gA[row * (D / 8) + seg];
            uint4 vb = gB[row * (D / 8) + seg];
            *reinterpret_cast<uint4*>(sA + row * SSTRIDE + seg * 8) = va;
            *reinterpret_cast<uint4*>(sB + row * SSTRIDE + seg * 8) = vb;
        }
    }
    __syncthreads();

    const uint32_t aBase = (uint32_t)__cvta_generic_to_shared(sA);
    const uint32_t bBase = (uint32_t)__cvta_generic_to_shared(sB);
    const int wm = (warp & 3) * 32;      // 4 warps along M
    const int wn = (warp >> 2) * 32;     // 4 warps along N

    float acc[2][4][4];
#pragma unroll
    for (int mt = 0; mt < 2; mt++)
#pragma unroll
        for (int nt = 0; nt < 4; nt++)
#pragma unroll
            for (int q = 0; q < 4; q++) acc[mt][nt][q] = 0.f;

#pragma unroll
    for (int kt = 0; kt < 8; kt++) {
        const int k0 = kt * 16;
        uint32_t afr[2][4];
#pragma unroll
        for (int mt = 0; mt < 2; mt++) {
            int row = wm + mt * 16 + (lane & 15);
            int col = k0 + (lane >> 4) * 8;
            ldmx4(afr[mt], aBase + (uint32_t)(row * SSTRIDE + col) * 2);
        }
#pragma unroll
        for (int np = 0; np < 2; np++) {         // each x4 covers two n8-tiles
            int g = lane >> 3;
            int nrow = wn + np * 16 + (g >> 1) * 8 + (lane & 7);
            int col = k0 + (g & 1) * 8;
            uint32_t r4[4];
            ldmx4(r4, bBase + (uint32_t)(nrow * SSTRIDE + col) * 2);
            mma16816(acc[0][np * 2 + 0], afr[0], r4[0], r4[1]);
            mma16816(acc[0][np * 2 + 1], afr[0], r4[2], r4[3]);
            mma16816(acc[1][np * 2 + 0], afr[1], r4[0], r4[1]);
            mma16816(acc[1][np * 2 + 1], afr[1], r4[2], r4[3]);
        }
    }

    // ---- epilogue ----
    const int rbase = i0 + wm + (lane >> 2);
    const int cbase = j0 + wn + 2 * (lane & 3);
    const bool has_diag = (!offdiag) && (wm == wn);

    float ccol[4][2];
#pragma unroll
    for (int nt = 0; nt < 4; nt++) { ccol[nt][0] = 0.f; ccol[nt][1] = 0.f; }

#pragma unroll
    for (int mt = 0; mt < 2; mt++) {
#pragma unroll
        for (int half = 0; half < 2; half++) {
            int grow = rbase + mt * 16 + half * 8;
            float p = 0.f;
            if (has_diag) {
#pragma unroll
                for (int nt = 0; nt < 4; nt++) {
                    int gc0 = cbase + nt * 8;
                    float e0 = (grow != gc0)
                             ? __expf(2.0f * acc[mt][nt][half * 2 + 0]) : 0.f;
                    float e1 = (grow != gc0 + 1)
                             ? __expf(2.0f * acc[mt][nt][half * 2 + 1]) : 0.f;
                    p += e0 + e1;
                }
            } else {
#pragma unroll
                for (int nt = 0; nt < 4; nt++) {
                    float e0 = __expf(2.0f * acc[mt][nt][half * 2 + 0]);
                    float e1 = __expf(2.0f * acc[mt][nt][half * 2 + 1]);
                    p += e0 + e1;
                    ccol[nt][0] += e0;
                    ccol[nt][1] += e1;
                }
            }
            p += __shfl_xor_sync(0xffffffffu, p, 1);
            p += __shfl_xor_sync(0xffffffffu, p, 2);
            if ((lane & 3) == 0) atomicAdd(&g_s.den[grow], p);
        }
    }

    if (offdiag) {
#pragma unroll
        for (int nt = 0; nt < 4; nt++) {
#pragma unroll
            for (int c = 0; c < 2; c++) {
                float v = ccol[nt][c];
                v += __shfl_xor_sync(0xffffffffu, v, 4);
                v += __shfl_xor_sync(0xffffffffu, v, 8);
                v += __shfl_xor_sync(0xffffffffu, v, 16);
                if (lane < 4) atomicAdd(&g_s.den[j0 + wn + nt * 8 + 2 * lane + c], v);
            }
        }
    }
}

// -------- kernel 3: loss = sum_j log(den[j]) - (2/N) * dot(sumz, sumzp) --------
__global__ void finalize_kernel(float* __restrict__ out) {
    int tid = threadIdx.x;
    if (blockIdx.x == 0 && tid == 0) out[0] = 0.f;
    int i = blockIdx.x * blockDim.x + tid;
    float v = __logf(g_s.den[i]);
    if (blockIdx.x == 1 && tid < D)
        v -= (2.0f / (float)N) * g_s.sumz[tid] * g_s.sumzp[tid];
#pragma unroll
    for (int o = 16; o > 0; o >>= 1) v += __shfl_xor_sync(0xffffffffu, v, o);
    if ((tid & 31) == 0) atomicAdd(out, v);
}

extern "C" void kernel_launch(void* const* d_in, const int* in_sizes, int n_in,
                              void* d_out, int out_size) {
    const float* nodes = (const float*)d_in[0];
    const float* pairn = (const float*)d_in[1];
    float* out = (float*)d_out;

    void* scratch_ptr = nullptr;
    cudaGetSymbolAddress(&scratch_ptr, g_s);
    cudaFuncSetAttribute(simexp_kernel, cudaFuncAttributeMaxDynamicSharedMemorySize, SMEM_BYTES);

    cudaMemsetAsync(scratch_ptr, 0, sizeof(Scratch));
    prep_kernel<<<2 * (N / 8), 256>>>(nodes, pairn);
    simexp_kernel<<<NUM_TRI, 512, SMEM_BYTES>>>();
    finalize_kernel<<<N / 256, 256>>>(out);
}

// round 9
// speedup vs baseline: 1.7373x; 1.0702x over previous
#include <cuda_runtime.h>
#include <cuda_bf16.h>
#include <cstdint>

#define N 8192
#define D 128
#define BM 128
#define BN 128
#define NT_TILES 64
#define NUM_TRI (NT_TILES * (NT_TILES + 1) / 2)   // 2080
#define SSTRIDE 136                                // 128 + 8 bf16 pad
#define SMEM_BYTES (2 * BM * SSTRIDE * 2)          // 69632

// -------- device scratch --------
__device__ __nv_bfloat16 g_zn[N * D];
struct Scratch { float sumz[D]; float sumzp[D]; };
__device__ Scratch g_s;
__device__ float g_den[N];

// -------- kernel 1: normalize rows -> bf16, column sums (register-accumulated),
//          zero g_den --------
// grid = 128 blocks: 0..63 nodes, 64..127 pair_nodes. 8 warps/block, 16 rows/warp.
__global__ void __launch_bounds__(256) prep_kernel(const float* __restrict__ nodes,
                                                   const float* __restrict__ pairn) {
    __shared__ float s_col[8][D];
    const int tid = threadIdx.x;
    const int warp = tid >> 5, lane = tid & 31;
    const bool is_pair = blockIdx.x >= 64;
    const int rb = (blockIdx.x & 63) * 128;
    const float* src = is_pair ? pairn : nodes;

    if (!is_pair && tid < 128) g_den[rb + tid] = 0.f;   // safe: simexp runs later

    float c0 = 0.f, c1 = 0.f, c2 = 0.f, c3 = 0.f;
    const int row0 = rb + warp * 16;
#pragma unroll 4
    for (int r = 0; r < 16; r++) {
        const int row = row0 + r;
        float4 v = reinterpret_cast<const float4*>(src + (size_t)row * D)[lane];
        float sq = v.x * v.x + v.y * v.y + v.z * v.z + v.w * v.w;
#pragma unroll
        for (int o = 16; o > 0; o >>= 1) sq += __shfl_xor_sync(0xffffffffu, sq, o);
        float scale = 1.0f / fmaxf(sqrtf(sq), 1e-12f);
        float z0 = v.x * scale, z1 = v.y * scale, z2 = v.z * scale, z3 = v.w * scale;
        if (!is_pair) {
            __nv_bfloat162* dst = reinterpret_cast<__nv_bfloat162*>(g_zn + (size_t)row * D);
            dst[lane * 2 + 0] = __floats2bfloat162_rn(z0, z1);
            dst[lane * 2 + 1] = __floats2bfloat162_rn(z2, z3);
        }
        c0 += z0; c1 += z1; c2 += z2; c3 += z3;
    }
    s_col[warp][lane * 4 + 0] = c0;
    s_col[warp][lane * 4 + 1] = c1;
    s_col[warp][lane * 4 + 2] = c2;
    s_col[warp][lane * 4 + 3] = c3;
    __syncthreads();
    if (tid < D) {
        float s = 0.f;
#pragma unroll
        for (int w = 0; w < 8; w++) s += s_col[w][tid];
        atomicAdd(is_pair ? &g_s.sumzp[tid] : &g_s.sumz[tid], s);
    }
}

// -------- mma helpers --------
__device__ __forceinline__ void ldmx4(uint32_t r[4], uint32_t addr) {
    asm volatile("ldmatrix.sync.aligned.m8n8.x4.shared.b16 {%0,%1,%2,%3}, [%4];\n"
                 : "=r"(r[0]), "=r"(r[1]), "=r"(r[2]), "=r"(r[3]) : "r"(addr));
}
__device__ __forceinline__ void mma16816(float c[4], const uint32_t a[4],
                                         uint32_t b0, uint32_t b1) {
    asm volatile("mma.sync.aligned.m16n8k16.row.col.f32.bf16.bf16.f32 "
                 "{%0,%1,%2,%3}, {%4,%5,%6,%7}, {%8,%9}, {%0,%1,%2,%3};\n"
                 : "+f"(c[0]), "+f"(c[1]), "+f"(c[2]), "+f"(c[3])
                 : "r"(a[0]), "r"(a[1]), "r"(a[2]), "r"(a[3]), "r"(b0), "r"(b1));
}

// -------- kernel 2: triangular tiles of S = ZN@ZN^T, fused exp, symmetry --------
__global__ void __launch_bounds__(512, 2) simexp_kernel() {
    extern __shared__ __nv_bfloat16 smem[];
    __nv_bfloat16* sA = smem;
    __nv_bfloat16* sB = smem + BM * SSTRIDE;

    const int tid = threadIdx.x;
    const int warp = tid >> 5, lane = tid & 31;

    // triangular decode t -> (ti, tj), tj >= ti
    const int t = blockIdx.x;
    int ti = (int)((129.0f - sqrtf(16641.0f - 8.0f * (float)t)) * 0.5f);
    if (ti > 0 && ti * (2 * NT_TILES + 1 - ti) / 2 > t) ti--;
    while ((ti + 1) * (2 * NT_TILES + 1 - (ti + 1)) / 2 <= t) ti++;
    const int tj = ti + (t - ti * (2 * NT_TILES + 1 - ti) / 2);
    const int i0 = ti * BM;
    const int j0 = tj * BN;
    const bool offdiag = (tj != ti);

    // cooperative tile loads: 512 threads, 16B vectors
    {
        const int r = tid >> 4;          // 0..31
        const int seg = tid & 15;        // 16B segment
        const uint4* gA = reinterpret_cast<const uint4*>(g_zn + (size_t)i0 * D);
        const uint4* gB = reinterpret_cast<const uint4*>(g_zn + (size_t)j0 * D);
#pragma unroll
        for (int rr = 0; rr < 4; rr++) {
            int row = r + rr * 32;
            uint4 va = gA[row * (D / 8) + seg];
            uint4 vb = gB[row * (D / 8) + seg];
            *reinterpret_cast<uint4*>(sA + row * SSTRIDE + seg * 8) = va;
            *reinterpret_cast<uint4*>(sB + row * SSTRIDE + seg * 8) = vb;
        }
    }
    __syncthreads();

    const uint32_t aBase = (uint32_t)__cvta_generic_to_shared(sA);
    const uint32_t bBase = (uint32_t)__cvta_generic_to_shared(sB);
    const int wm = (warp & 3) * 32;      // 4 warps along M
    const int wn = (warp >> 2) * 32;     // 4 warps along N

    float acc[2][4][4];
#pragma unroll
    for (int mt = 0; mt < 2; mt++)
#pragma unroll
        for (int nt = 0; nt < 4; nt++)
#pragma unroll
            for (int q = 0; q < 4; q++) acc[mt][nt][q] = 0.f;

#pragma unroll
    for (int kt = 0; kt < 8; kt++) {
        const int k0 = kt * 16;
        uint32_t afr[2][4];
#pragma unroll
        for (int mt = 0; mt < 2; mt++) {
            int row = wm + mt * 16 + (lane & 15);
            int col = k0 + (lane >> 4) * 8;
            ldmx4(afr[mt], aBase + (uint32_t)(row * SSTRIDE + col) * 2);
        }
#pragma unroll
        for (int np = 0; np < 2; np++) {         // each x4 covers two n8-tiles
            int g = lane >> 3;
            int nrow = wn + np * 16 + (g >> 1) * 8 + (lane & 7);
            int col = k0 + (g & 1) * 8;
            uint32_t r4[4];
            ldmx4(r4, bBase + (uint32_t)(nrow * SSTRIDE + col) * 2);
            mma16816(acc[0][np * 2 + 0], afr[0], r4[0], r4[1]);
            mma16816(acc[0][np * 2 + 1], afr[0], r4[2], r4[3]);
            mma16816(acc[1][np * 2 + 0], afr[1], r4[0], r4[1]);
            mma16816(acc[1][np * 2 + 1], afr[1], r4[2], r4[3]);
        }
    }

    // ---- epilogue ----
    const int rbase = i0 + wm + (lane >> 2);
    const int cbase = j0 + wn + 2 * (lane & 3);
    const bool has_diag = (!offdiag) && (wm == wn);

    float ccol[4][2];
#pragma unroll
    for (int nt = 0; nt < 4; nt++) { ccol[nt][0] = 0.f; ccol[nt][1] = 0.f; }

#pragma unroll
    for (int mt = 0; mt < 2; mt++) {
#pragma unroll
        for (int half = 0; half < 2; half++) {
            int grow = rbase + mt * 16 + half * 8;
            float p = 0.f;
            if (has_diag) {
#pragma unroll
                for (int nt = 0; nt < 4; nt++) {
                    int gc0 = cbase + nt * 8;
                    float e0 = (grow != gc0)
                             ? __expf(2.0f * acc[mt][nt][half * 2 + 0]) : 0.f;
                    float e1 = (grow != gc0 + 1)
                             ? __expf(2.0f * acc[mt][nt][half * 2 + 1]) : 0.f;
                    p += e0 + e1;
                }
            } else {
#pragma unroll
                for (int nt = 0; nt < 4; nt++) {
                    float e0 = __expf(2.0f * acc[mt][nt][half * 2 + 0]);
                    float e1 = __expf(2.0f * acc[mt][nt][half * 2 + 1]);
                    p += e0 + e1;
                    ccol[nt][0] += e0;
                    ccol[nt][1] += e1;
                }
            }
            p += __shfl_xor_sync(0xffffffffu, p, 1);
            p += __shfl_xor_sync(0xffffffffu, p, 2);
            if ((lane & 3) == 0) atomicAdd(&g_den[grow], p);
        }
    }

    if (offdiag) {
#pragma unroll
        for (int nt = 0; nt < 4; nt++) {
#pragma unroll
            for (int c = 0; c < 2; c++) {
                float v = ccol[nt][c];
                v += __shfl_xor_sync(0xffffffffu, v, 4);
                v += __shfl_xor_sync(0xffffffffu, v, 8);
                v += __shfl_xor_sync(0xffffffffu, v, 16);
                if (lane < 4) atomicAdd(&g_den[j0 + wn + nt * 8 + 2 * lane + c], v);
            }
        }
    }
}

// -------- kernel 3: loss = sum_j log(den[j]) - (2/N) * dot(sumz, sumzp) --------
// out[0] is pre-zeroed by cudaMemsetAsync (no in-kernel race).
__global__ void finalize_kernel(float* __restrict__ out) {
    int tid = threadIdx.x;
    int i = blockIdx.x * blockDim.x + tid;
    float v = __logf(g_den[i]);
    if (blockIdx.x == 0 && tid < D)
        v -= (2.0f / (float)N) * g_s.sumz[tid] * g_s.sumzp[tid];
#pragma unroll
    for (int o = 16; o > 0; o >>= 1) v += __shfl_xor_sync(0xffffffffu, v, o);
    if ((tid & 31) == 0) atomicAdd(out, v);
}

extern "C" void kernel_launch(void* const* d_in, const int* in_sizes, int n_in,
                              void* d_out, int out_size) {
    const float* nodes = (const float*)d_in[0];
    const float* pairn = (const float*)d_in[1];
    float* out = (float*)d_out;

    void* scratch_ptr = nullptr;
    cudaGetSymbolAddress(&scratch_ptr, g_s);
    cudaFuncSetAttribute(simexp_kernel, cudaFuncAttributeMaxDynamicSharedMemorySize, SMEM_BYTES);

    cudaMemsetAsync(scratch_ptr, 0, sizeof(Scratch));
    cudaMemsetAsync(out, 0, sizeof(float));
    prep_kernel<<<128, 256>>>(nodes, pairn);
    simexp_kernel<<<NUM_TRI, 512, SMEM_BYTES>>>();
    finalize_kernel<<<N / 256, 256>>>(out);
}

// round 10
// speedup vs baseline: 1.8114x; 1.0427x over previous
#include <cuda_runtime.h>
#include <cuda_bf16.h>
#include <cstdint>

#define N 8192
#define D 128
#define BM 128
#define BN 128
#define NT_TILES 64
#define NUM_TRI (NT_TILES * (NT_TILES + 1) / 2)   // 2080
#define SSTRIDE 136                                // 128 + 8 bf16 pad
#define SMEM_BYTES (2 * BM * SSTRIDE * 2)          // 69632

// -------- device scratch --------
__device__ __nv_bfloat16 g_zn[N * D];
struct Scratch { float sumz[D]; float sumzp[D]; };
__device__ Scratch g_s;
__device__ float g_den[N];

// -------- kernel 1: normalize rows -> bf16, column sums, zero g_den --------
// grid = 512 blocks: 0..255 nodes, 256..511 pair_nodes. 8 warps/block, 4 rows/warp
// (all 4 row-loads issued up-front for MLP).
__global__ void __launch_bounds__(256) prep_kernel(const float* __restrict__ nodes,
                                                   const float* __restrict__ pairn) {
    __shared__ float s_col[8][D];
    const int tid = threadIdx.x;
    const int warp = tid >> 5, lane = tid & 31;
    const bool is_pair = blockIdx.x >= 256;
    const int rb = (blockIdx.x & 255) * 32;        // 32 rows per block
    const float* src = is_pair ? pairn : nodes;

    if (!is_pair && tid < 32) g_den[rb + tid] = 0.f;   // safe: simexp runs later

    const int row0 = rb + warp * 4;

    // issue all 4 independent row loads first (MLP = 4)
    float4 v[4];
#pragma unroll
    for (int r = 0; r < 4; r++)
        v[r] = reinterpret_cast<const float4*>(src + (size_t)(row0 + r) * D)[lane];

    float c0 = 0.f, c1 = 0.f, c2 = 0.f, c3 = 0.f;
#pragma unroll
    for (int r = 0; r < 4; r++) {
        float sq = v[r].x * v[r].x + v[r].y * v[r].y + v[r].z * v[r].z + v[r].w * v[r].w;
#pragma unroll
        for (int o = 16; o > 0; o >>= 1) sq += __shfl_xor_sync(0xffffffffu, sq, o);
        float scale = 1.0f / fmaxf(sqrtf(sq), 1e-12f);
        float z0 = v[r].x * scale, z1 = v[r].y * scale;
        float z2 = v[r].z * scale, z3 = v[r].w * scale;
        if (!is_pair) {
            __nv_bfloat162* dst =
                reinterpret_cast<__nv_bfloat162*>(g_zn + (size_t)(row0 + r) * D);
            dst[lane * 2 + 0] = __floats2bfloat162_rn(z0, z1);
            dst[lane * 2 + 1] = __floats2bfloat162_rn(z2, z3);
        }
        c0 += z0; c1 += z1; c2 += z2; c3 += z3;
    }
    s_col[warp][lane * 4 + 0] = c0;
    s_col[warp][lane * 4 + 1] = c1;
    s_col[warp][lane * 4 + 2] = c2;
    s_col[warp][lane * 4 + 3] = c3;
    __syncthreads();
    if (tid < D) {
        float s = 0.f;
#pragma unroll
        for (int w = 0; w < 8; w++) s += s_col[w][tid];
        atomicAdd(is_pair ? &g_s.sumzp[tid] : &g_s.sumz[tid], s);
    }
}

// -------- mma helpers --------
__device__ __forceinline__ void ldmx4(uint32_t r[4], uint32_t addr) {
    asm volatile("ldmatrix.sync.aligned.m8n8.x4.shared.b16 {%0,%1,%2,%3}, [%4];\n"
                 : "=r"(r[0]), "=r"(r[1]), "=r"(r[2]), "=r"(r[3]) : "r"(addr));
}
__device__ __forceinline__ void mma16816(float c[4], const uint32_t a[4],
                                         uint32_t b0, uint32_t b1) {
    asm volatile("mma.sync.aligned.m16n8k16.row.col.f32.bf16.bf16.f32 "
                 "{%0,%1,%2,%3}, {%4,%5,%6,%7}, {%8,%9}, {%0,%1,%2,%3};\n"
                 : "+f"(c[0]), "+f"(c[1]), "+f"(c[2]), "+f"(c[3])
                 : "r"(a[0]), "r"(a[1]), "r"(a[2]), "r"(a[3]), "r"(b0), "r"(b1));
}

// -------- kernel 2: triangular tiles of S = ZN@ZN^T, fused exp, symmetry --------
__global__ void __launch_bounds__(512, 2) simexp_kernel() {
    extern __shared__ __nv_bfloat16 smem[];
    __nv_bfloat16* sA = smem;
    __nv_bfloat16* sB = smem + BM * SSTRIDE;

    const int tid = threadIdx.x;
    const int warp = tid >> 5, lane = tid & 31;

    // triangular decode t -> (ti, tj), tj >= ti
    const int t = blockIdx.x;
    int ti = (int)((129.0f - sqrtf(16641.0f - 8.0f * (float)t)) * 0.5f);
    if (ti > 0 && ti * (2 * NT_TILES + 1 - ti) / 2 > t) ti--;
    while ((ti + 1) * (2 * NT_TILES + 1 - (ti + 1)) / 2 <= t) ti++;
    const int tj = ti + (t - ti * (2 * NT_TILES + 1 - ti) / 2);
    const int i0 = ti * BM;
    const int j0 = tj * BN;
    const bool offdiag = (tj != ti);

    // cooperative tile loads: 512 threads, 16B vectors
    {
        const int r = tid >> 4;          // 0..31
        const int seg = tid & 15;        // 16B segment
        const uint4* gA = reinterpret_cast<const uint4*>(g_zn + (size_t)i0 * D);
        const uint4* gB = reinterpret_cast<const uint4*>(g_zn + (size_t)j0 * D);
#pragma unroll
        for (int rr = 0; rr < 4; rr++) {
            int row = r + rr * 32;
            uint4 va = gA[row * (D / 8) + seg];
            uint4 vb = gB[row * (D / 8) + seg];
            *reinterpret_cast<uint4*>(sA + row * SSTRIDE + seg * 8) = va;
            *reinterpret_cast<uint4*>(sB + row * SSTRIDE + seg * 8) = vb;
        }
    }
    __syncthreads();

    const uint32_t aBase = (uint32_t)__cvta_generic_to_shared(sA);
    const uint32_t bBase = (uint32_t)__cvta_generic_to_shared(sB);
    const int wm = (warp & 3) * 32;      // 4 warps along M
    const int wn = (warp >> 2) * 32;     // 4 warps along N

    float acc[2][4][4];
#pragma unroll
    for (int mt = 0; mt < 2; mt++)
#pragma unroll
        for (int nt = 0; nt < 4; nt++)
#pragma unroll
            for (int q = 0; q < 4; q++) acc[mt][nt][q] = 0.f;

#pragma unroll
    for (int kt = 0; kt < 8; kt++) {
        const int k0 = kt * 16;
        uint32_t afr[2][4];
#pragma unroll
        for (int mt = 0; mt < 2; mt++) {
            int row = wm + mt * 16 + (lane & 15);
            int col = k0 + (lane >> 4) * 8;
            ldmx4(afr[mt], aBase + (uint32_t)(row * SSTRIDE + col) * 2);
        }
#pragma unroll
        for (int np = 0; np < 2; np++) {         // each x4 covers two n8-tiles
            int g = lane >> 3;
            int nrow = wn + np * 16 + (g >> 1) * 8 + (lane & 7);
            int col = k0 + (g & 1) * 8;
            uint32_t r4[4];
            ldmx4(r4, bBase + (uint32_t)(nrow * SSTRIDE + col) * 2);
            mma16816(acc[0][np * 2 + 0], afr[0], r4[0], r4[1]);
            mma16816(acc[0][np * 2 + 1], afr[0], r4[2], r4[3]);
            mma16816(acc[1][np * 2 + 0], afr[1], r4[0], r4[1]);
            mma16816(acc[1][np * 2 + 1], afr[1], r4[2], r4[3]);
        }
    }

    // ---- epilogue ----
    const int rbase = i0 + wm + (lane >> 2);
    const int cbase = j0 + wn + 2 * (lane & 3);
    const bool has_diag = (!offdiag) && (wm == wn);

    float ccol[4][2];
#pragma unroll
    for (int nt = 0; nt < 4; nt++) { ccol[nt][0] = 0.f; ccol[nt][1] = 0.f; }

#pragma unroll
    for (int mt = 0; mt < 2; mt++) {
#pragma unroll
        for (int half = 0; half < 2; half++) {
            int grow = rbase + mt * 16 + half * 8;
            float p = 0.f;
            if (has_diag) {
#pragma unroll
                for (int nt = 0; nt < 4; nt++) {
                    int gc0 = cbase + nt * 8;
                    float e0 = (grow != gc0)
                             ? __expf(2.0f * acc[mt][nt][half * 2 + 0]) : 0.f;
                    float e1 = (grow != gc0 + 1)
                             ? __expf(2.0f * acc[mt][nt][half * 2 + 1]) : 0.f;
                    p += e0 + e1;
                }
            } else {
#pragma unroll
                for (int nt = 0; nt < 4; nt++) {
                    float e0 = __expf(2.0f * acc[mt][nt][half * 2 + 0]);
                    float e1 = __expf(2.0f * acc[mt][nt][half * 2 + 1]);
                    p += e0 + e1;
                    ccol[nt][0] += e0;
                    ccol[nt][1] += e1;
                }
            }
            p += __shfl_xor_sync(0xffffffffu, p, 1);
            p += __shfl_xor_sync(0xffffffffu, p, 2);
            if ((lane & 3) == 0) atomicAdd(&g_den[grow], p);
        }
    }

    if (offdiag) {
#pragma unroll
        for (int nt = 0; nt < 4; nt++) {
#pragma unroll
            for (int c = 0; c < 2; c++) {
                float v = ccol[nt][c];
                v += __shfl_xor_sync(0xffffffffu, v, 4);
                v += __shfl_xor_sync(0xffffffffu, v, 8);
                v += __shfl_xor_sync(0xffffffffu, v, 16);
                if (lane < 4) atomicAdd(&g_den[j0 + wn + nt * 8 + 2 * lane + c], v);
            }
        }
    }
}

// -------- kernel 3: loss = sum_j log(den[j]) - (2/N) * dot(sumz, sumzp) --------
// out[0] is pre-zeroed by cudaMemsetAsync (no in-kernel race).
__global__ void finalize_kernel(float* __restrict__ out) {
    int tid = threadIdx.x;
    int i = blockIdx.x * blockDim.x + tid;
    float v = __logf(g_den[i]);
    if (blockIdx.x == 0 && tid < D)
        v -= (2.0f / (float)N) * g_s.sumz[tid] * g_s.sumzp[tid];
#pragma unroll
    for (int o = 16; o > 0; o >>= 1) v += __shfl_xor_sync(0xffffffffu, v, o);
    if ((tid & 31) == 0) atomicAdd(out, v);
}

extern "C" void kernel_launch(void* const* d_in, const int* in_sizes, int n_in,
                              void* d_out, int out_size) {
    const float* nodes = (const float*)d_in[0];
    const float* pairn = (const float*)d_in[1];
    float* out = (float*)d_out;

    void* scratch_ptr = nullptr;
    cudaGetSymbolAddress(&scratch_ptr, g_s);
    cudaFuncSetAttribute(simexp_kernel, cudaFuncAttributeMaxDynamicSharedMemorySize, SMEM_BYTES);

    cudaMemsetAsync(scratch_ptr, 0, sizeof(Scratch));
    cudaMemsetAsync(out, 0, sizeof(float));
    prep_kernel<<<512, 256>>>(nodes, pairn);
    simexp_kernel<<<NUM_TRI, 512, SMEM_BYTES>>>();
    finalize_kernel<<<N / 256, 256>>>(out);
}